// round 2
// baseline (speedup 1.0000x reference)
#include <cuda_runtime.h>

// ---------------- Problem constants ----------------
#define TILE_M   16
#define NTHREADS 256
#define DSTATE   256
#define DIN      512
#define NWIDTH   512
#define NSTEPS   60
#define NBLOCKS  128   // 2048 rows / TILE_M

// Tsit5 tableau
__constant__ float c_A[6][5] = {
    {0.f, 0.f, 0.f, 0.f, 0.f},
    {0.161f, 0.f, 0.f, 0.f, 0.f},
    {-0.008480655492356989f, 0.335480655492357f, 0.f, 0.f, 0.f},
    {2.8971530571054935f, -6.359448489975075f, 4.3622954328695815f, 0.f, 0.f},
    {5.325864828439257f, -11.748883564062828f, 7.4955393428898365f, -0.09249506636175525f, 0.f},
    {5.86145544294642f, -12.92096931784711f, 8.159367898576159f, -0.071584973281401f, -0.028269050394068383f}};
__constant__ float c_B[6] = {
    0.09646076681806523f, 0.01f, 0.4798896504144996f,
    1.379008574103742f, -3.290069515436081f, 2.324710524099774f};

// Transposed weight scratch (L2-resident), [k][n] layout
__device__ float g_W1T[DIN * NWIDTH];
__device__ float g_W2T[NWIDTH * NWIDTH];
__device__ float g_W3T[NWIDTH * DSTATE];

// ---------------- packed f32x2 helpers ----------------
static __device__ __forceinline__ unsigned long long pk2(float x, float y) {
    unsigned long long d;
    asm("mov.b64 %0, {%1, %2};" : "=l"(d) : "f"(x), "f"(y));
    return d;
}
static __device__ __forceinline__ unsigned long long fma2(unsigned long long a,
                                                          unsigned long long b,
                                                          unsigned long long c) {
    unsigned long long d;
    asm("fma.rn.f32x2 %0, %1, %2, %3;" : "=l"(d) : "l"(a), "l"(b), "l"(c));
    return d;
}
static __device__ __forceinline__ void upk2(unsigned long long v, float& x, float& y) {
    asm("mov.b64 {%0, %1}, %2;" : "=f"(x), "=f"(y) : "l"(v));
}

// ---------------- weight transpose: src[N][K] -> dst[K][N] ----------------
__global__ void transpose_kernel(int which, const float* __restrict__ src, int N, int K) {
    float* dst = (which == 0) ? g_W1T : (which == 1) ? g_W2T : g_W3T;
    __shared__ float tile[32][33];
    int kb = blockIdx.x * 32;
    int nb = blockIdx.y * 32;
    int tx = threadIdx.x, ty = threadIdx.y;  // 32 x 8
    #pragma unroll
    for (int i = ty; i < 32; i += 8) {
        tile[i][tx] = src[(nb + i) * K + (kb + tx)];  // coalesced over k
    }
    __syncthreads();
    #pragma unroll
    for (int i = ty; i < 32; i += 8) {
        dst[(kb + i) * N + (nb + tx)] = tile[tx][i];  // coalesced over n
    }
}

// ---------------- GEMM micro-kernels (per-CTA, A in SMEM m-major) ----------------
// N=512 layer: A[16][512] -> A[16][512] (in place after full read), relu, +bias
static __device__ __forceinline__ void gemmN512(float* A, const float* __restrict__ WT,
                                                const float* __restrict__ bias,
                                                int m0, int n0, bool do_relu) {
    unsigned long long acc[4][4];
    {
        float4 bb0 = *reinterpret_cast<const float4*>(bias + n0);
        float4 bb1 = *reinterpret_cast<const float4*>(bias + n0 + 4);
        unsigned long long bi[4] = {pk2(bb0.x, bb0.y), pk2(bb0.z, bb0.w),
                                    pk2(bb1.x, bb1.y), pk2(bb1.z, bb1.w)};
        #pragma unroll
        for (int mi = 0; mi < 4; ++mi)
            #pragma unroll
            for (int pj = 0; pj < 4; ++pj) acc[mi][pj] = bi[pj];
    }
    #pragma unroll 8
    for (int k = 0; k < DIN; ++k) {
        unsigned long long ad[4];
        #pragma unroll
        for (int mi = 0; mi < 4; ++mi) {
            float a = A[(m0 + mi) * DIN + k];  // LDS broadcast within warp
            ad[mi] = pk2(a, a);
        }
        float4 w0 = *reinterpret_cast<const float4*>(WT + (size_t)k * NWIDTH + n0);
        float4 w1 = *reinterpret_cast<const float4*>(WT + (size_t)k * NWIDTH + n0 + 4);
        unsigned long long wp[4] = {pk2(w0.x, w0.y), pk2(w0.z, w0.w),
                                    pk2(w1.x, w1.y), pk2(w1.z, w1.w)};
        #pragma unroll
        for (int mi = 0; mi < 4; ++mi)
            #pragma unroll
            for (int pj = 0; pj < 4; ++pj) acc[mi][pj] = fma2(ad[mi], wp[pj], acc[mi][pj]);
    }
    __syncthreads();  // all reads of A complete before overwrite
    #pragma unroll
    for (int mi = 0; mi < 4; ++mi) {
        float o[8];
        #pragma unroll
        for (int pj = 0; pj < 4; ++pj) upk2(acc[mi][pj], o[2 * pj], o[2 * pj + 1]);
        if (do_relu) {
            #pragma unroll
            for (int t = 0; t < 8; ++t) o[t] = fmaxf(o[t], 0.f);
        }
        float4 v0 = make_float4(o[0], o[1], o[2], o[3]);
        float4 v1 = make_float4(o[4], o[5], o[6], o[7]);
        *reinterpret_cast<float4*>(A + (m0 + mi) * DIN + n0) = v0;
        *reinterpret_cast<float4*>(A + (m0 + mi) * DIN + n0 + 4) = v1;
    }
    __syncthreads();
}

// N=256 layer: A[16][512] -> dst[16][256] (k-slot), +bias, no relu
static __device__ __forceinline__ void gemmN256(const float* A, const float* __restrict__ WT,
                                                const float* __restrict__ bias,
                                                float* dst, int m0, int n0) {
    unsigned long long acc[4][2];
    {
        float4 bb = *reinterpret_cast<const float4*>(bias + n0);
        unsigned long long bi[2] = {pk2(bb.x, bb.y), pk2(bb.z, bb.w)};
        #pragma unroll
        for (int mi = 0; mi < 4; ++mi) {
            acc[mi][0] = bi[0];
            acc[mi][1] = bi[1];
        }
    }
    #pragma unroll 8
    for (int k = 0; k < DIN; ++k) {
        unsigned long long ad[4];
        #pragma unroll
        for (int mi = 0; mi < 4; ++mi) {
            float a = A[(m0 + mi) * DIN + k];
            ad[mi] = pk2(a, a);
        }
        float4 w = *reinterpret_cast<const float4*>(WT + (size_t)k * DSTATE + n0);
        unsigned long long wp[2] = {pk2(w.x, w.y), pk2(w.z, w.w)};
        #pragma unroll
        for (int mi = 0; mi < 4; ++mi) {
            acc[mi][0] = fma2(ad[mi], wp[0], acc[mi][0]);
            acc[mi][1] = fma2(ad[mi], wp[1], acc[mi][1]);
        }
    }
    __syncthreads();  // all reads of A done (next z-build will overwrite A)
    #pragma unroll
    for (int mi = 0; mi < 4; ++mi) {
        float o[4];
        upk2(acc[mi][0], o[0], o[1]);
        upk2(acc[mi][1], o[2], o[3]);
        float4 v = make_float4(o[0], o[1], o[2], o[3]);
        *reinterpret_cast<float4*>(dst + (m0 + mi) * DSTATE + n0) = v;
    }
    __syncthreads();
}

// ---------------- main fused Tsit5 kernel ----------------
__global__ void __launch_bounds__(NTHREADS, 1)
ode_main(const float* __restrict__ x0, const float* __restrict__ uf,
         const float* __restrict__ b1, const float* __restrict__ b2,
         const float* __restrict__ b3, float* __restrict__ out) {
    extern __shared__ float smem[];
    float* A  = smem;                       // [16][512] activations / z
    float* U  = A + TILE_M * DIN;           // [16][256] forcing (constant)
    float* Y  = U + TILE_M * DSTATE;        // [16][256] state
    float* Kb = Y + TILE_M * DSTATE;        // [6][16][256] stage derivatives

    const int tid = threadIdx.x;
    const int r0 = blockIdx.x * TILE_M;

    // init y, u
    for (int idx = tid; idx < TILE_M * DSTATE; idx += NTHREADS) {
        int m = idx >> 8, c = idx & 255;
        int r = r0 + m, traj = r & 1023;
        Y[m * DSTATE + c] = x0[traj * DSTATE + c];
        U[m * DSTATE + c] = (r < 1024) ? uf[traj * DSTATE + c] : 0.f;
    }
    __syncthreads();

    const float H = 1.0f / 60.0f;
    const int m0 = (tid >> 6) * 4;
    const int n0_8 = (tid & 63) * 8;
    const int n0_4 = (tid & 63) * 4;
    const int c = tid;  // NTHREADS == DSTATE

    for (int step = 0; step < NSTEPS; ++step) {
        for (int s = 0; s < 6; ++s) {
            // build stage input z into A: [y + H*sum a_sj k_j | u]
            for (int m = 0; m < TILE_M; ++m) {
                float acc = 0.f;
                for (int j = 0; j < s; ++j)
                    acc += c_A[s][j] * Kb[(j * TILE_M + m) * DSTATE + c];
                A[m * DIN + c] = Y[m * DSTATE + c] + H * acc;
                A[m * DIN + DSTATE + c] = U[m * DSTATE + c];
            }
            __syncthreads();

            gemmN512(A, g_W1T, b1, m0, n0_8, true);
            gemmN512(A, g_W2T, b2, m0, n0_8, true);
            gemmN256(A, g_W3T, b3, Kb + s * TILE_M * DSTATE, m0, n0_4);
        }
        // y += H * sum b_i k_i
        for (int m = 0; m < TILE_M; ++m) {
            float acc = 0.f;
            #pragma unroll
            for (int j = 0; j < 6; ++j)
                acc += c_B[j] * Kb[(j * TILE_M + m) * DSTATE + c];
            Y[m * DSTATE + c] += H * acc;
        }
        __syncthreads();
    }

    // out[(branch*1024 + traj)*256 + c] == out[r*256 + c]
    for (int idx = tid; idx < TILE_M * DSTATE; idx += NTHREADS) {
        int m = idx >> 8, cc = idx & 255;
        int r = r0 + m;
        out[(size_t)r * DSTATE + cc] = Y[m * DSTATE + cc];
    }
}

// ---------------- launch ----------------
extern "C" void kernel_launch(void* const* d_in, const int* in_sizes, int n_in,
                              void* d_out, int out_size) {
    (void)in_sizes; (void)n_in; (void)out_size;
    const float* x0 = (const float*)d_in[0];
    const float* uf = (const float*)d_in[1];
    const float* W1 = (const float*)d_in[2];
    const float* b1 = (const float*)d_in[3];
    const float* W2 = (const float*)d_in[4];
    const float* b2 = (const float*)d_in[5];
    const float* W3 = (const float*)d_in[6];
    const float* b3 = (const float*)d_in[7];
    float* out = (float*)d_out;

    dim3 tthreads(32, 8);
    transpose_kernel<<<dim3(DIN / 32, NWIDTH / 32), tthreads>>>(0, W1, NWIDTH, DIN);
    transpose_kernel<<<dim3(NWIDTH / 32, NWIDTH / 32), tthreads>>>(1, W2, NWIDTH, NWIDTH);
    transpose_kernel<<<dim3(NWIDTH / 32, DSTATE / 32), tthreads>>>(2, W3, DSTATE, NWIDTH);

    size_t smem_bytes = (size_t)(TILE_M * DIN + 2 * TILE_M * DSTATE + 6 * TILE_M * DSTATE) * sizeof(float);
    cudaFuncSetAttribute(ode_main, cudaFuncAttributeMaxDynamicSharedMemorySize, (int)smem_bytes);
    ode_main<<<NBLOCKS, NTHREADS, smem_bytes>>>(x0, uf, b1, b2, b3, out);
}

// round 3
// speedup vs baseline: 1.3822x; 1.3822x over previous
#include <cuda_runtime.h>

// ---------------- Problem constants ----------------
#define TM      16      // rows per CTA
#define NTH     512     // threads per CTA
#define DSTATE  256
#define DIN     512
#define NW      512
#define NSTEPS  60
#define NBLOCKS 128     // 2048 rows / TM

typedef unsigned long long u64;

// Tsit5 tableau
__constant__ float c_A[6][5] = {
    {0.f, 0.f, 0.f, 0.f, 0.f},
    {0.161f, 0.f, 0.f, 0.f, 0.f},
    {-0.008480655492356989f, 0.335480655492357f, 0.f, 0.f, 0.f},
    {2.8971530571054935f, -6.359448489975075f, 4.3622954328695815f, 0.f, 0.f},
    {5.325864828439257f, -11.748883564062828f, 7.4955393428898365f, -0.09249506636175525f, 0.f},
    {5.86145544294642f, -12.92096931784711f, 8.159367898576159f, -0.071584973281401f, -0.028269050394068383f}};
__constant__ float c_Bw[6] = {
    0.09646076681806523f, 0.01f, 0.4798896504144996f,
    1.379008574103742f, -3.290069515436081f, 2.324710524099774f};

// Transposed weight scratch (L2-resident), [k][n] layout
__device__ float g_W1T[DIN * NW];
__device__ float g_W2T[NW * NW];
__device__ float g_W3T[NW * DSTATE];

// ---------------- packed f32x2 helpers ----------------
static __device__ __forceinline__ u64 pk2(float x, float y) {
    u64 d;
    asm("mov.b64 %0, {%1, %2};" : "=l"(d) : "f"(x), "f"(y));
    return d;
}
static __device__ __forceinline__ u64 fma2(u64 a, u64 b, u64 c) {
    u64 d;
    asm("fma.rn.f32x2 %0, %1, %2, %3;" : "=l"(d) : "l"(a), "l"(b), "l"(c));
    return d;
}
static __device__ __forceinline__ void upk2(u64 v, float& x, float& y) {
    asm("mov.b64 {%0, %1}, %2;" : "=f"(x), "=f"(y) : "l"(v));
}

// ---------------- weight transpose: src[N][K] -> dst[K][N] ----------------
__global__ void transpose_kernel(int which, const float* __restrict__ src, int N, int K) {
    float* dst = (which == 0) ? g_W1T : (which == 1) ? g_W2T : g_W3T;
    __shared__ float tile[32][33];
    int kb = blockIdx.x * 32;
    int nb = blockIdx.y * 32;
    int tx = threadIdx.x, ty = threadIdx.y;  // 32 x 8
    #pragma unroll
    for (int i = ty; i < 32; i += 8)
        tile[i][tx] = src[(nb + i) * K + (kb + tx)];
    __syncthreads();
    #pragma unroll
    for (int i = ty; i < 32; i += 8)
        dst[(kb + i) * N + (nb + tx)] = tile[tx][i];
}

// ---------------- GEMM micro-kernels ----------------
// N=512 layer. Ain: SMEM k-major [K][16]. WT: global [*, 512] (row k, n contiguous).
// Each thread: 4 m (as 2 f32x2 pairs) x 4 n. m0 = (tid&3)*4, n0 = (tid>>2)*4.
// Output Aout k-major [512][16]. No internal sync; caller syncs after.
template <int K, bool RELU, bool INITSM>
static __device__ __forceinline__ void gemm512(
    const float* __restrict__ Ain, const float* __restrict__ WT,
    const float* __restrict__ bias_g, const float* __restrict__ initNM,
    float* __restrict__ Aout, int m0, int n0) {
    u64 acc[2][4];
    if (INITSM) {
        #pragma unroll
        for (int nj = 0; nj < 4; ++nj) {
            acc[0][nj] = *reinterpret_cast<const u64*>(initNM + (n0 + nj) * TM + m0);
            acc[1][nj] = *reinterpret_cast<const u64*>(initNM + (n0 + nj) * TM + m0 + 2);
        }
    } else {
        float4 b = *reinterpret_cast<const float4*>(bias_g + n0);
        u64 d0 = pk2(b.x, b.x), d1 = pk2(b.y, b.y), d2 = pk2(b.z, b.z), d3 = pk2(b.w, b.w);
        acc[0][0] = d0; acc[1][0] = d0;
        acc[0][1] = d1; acc[1][1] = d1;
        acc[0][2] = d2; acc[1][2] = d2;
        acc[0][3] = d3; acc[1][3] = d3;
    }
    const float* wp = WT + n0;
    #pragma unroll 8
    for (int k = 0; k < K; ++k) {
        // 4 m values as two ready f32x2 pairs (LDS.128, 16B-aligned)
        ulonglong2 av = *reinterpret_cast<const ulonglong2*>(Ain + k * TM + m0);
        // one 128B line per warp (lanes 0-3 share address -> L1 dedup)
        float4 w = *reinterpret_cast<const float4*>(wp + (size_t)k * NW);
        u64 wd0 = pk2(w.x, w.x), wd1 = pk2(w.y, w.y);
        u64 wd2 = pk2(w.z, w.z), wd3 = pk2(w.w, w.w);
        acc[0][0] = fma2(av.x, wd0, acc[0][0]); acc[1][0] = fma2(av.y, wd0, acc[1][0]);
        acc[0][1] = fma2(av.x, wd1, acc[0][1]); acc[1][1] = fma2(av.y, wd1, acc[1][1]);
        acc[0][2] = fma2(av.x, wd2, acc[0][2]); acc[1][2] = fma2(av.y, wd2, acc[1][2]);
        acc[0][3] = fma2(av.x, wd3, acc[0][3]); acc[1][3] = fma2(av.y, wd3, acc[1][3]);
    }
    #pragma unroll
    for (int nj = 0; nj < 4; ++nj) {
        float x0, x1, x2, x3;
        upk2(acc[0][nj], x0, x1);
        upk2(acc[1][nj], x2, x3);
        if (RELU) {
            x0 = fmaxf(x0, 0.f); x1 = fmaxf(x1, 0.f);
            x2 = fmaxf(x2, 0.f); x3 = fmaxf(x3, 0.f);
        }
        *reinterpret_cast<float4*>(Aout + (n0 + nj) * TM + m0) = make_float4(x0, x1, x2, x3);
    }
}

// N=256 layer (W3). Each thread: 2 m (one pair) x 4 n. m3=(tid&7)*2, n3=(tid>>3)*4.
static __device__ __forceinline__ void gemm256(
    const float* __restrict__ Ain, const float* __restrict__ WT,
    const float* __restrict__ bias_g, float* __restrict__ Kout, int m3, int n3) {
    u64 acc[4];
    float4 b = *reinterpret_cast<const float4*>(bias_g + n3);
    acc[0] = pk2(b.x, b.x); acc[1] = pk2(b.y, b.y);
    acc[2] = pk2(b.z, b.z); acc[3] = pk2(b.w, b.w);
    const float* wp = WT + n3;
    #pragma unroll 8
    for (int k = 0; k < DIN; ++k) {
        u64 ap = *reinterpret_cast<const u64*>(Ain + k * TM + m3);  // LDS.64, m pair
        float4 w = *reinterpret_cast<const float4*>(wp + (size_t)k * DSTATE);
        acc[0] = fma2(ap, pk2(w.x, w.x), acc[0]);
        acc[1] = fma2(ap, pk2(w.y, w.y), acc[1]);
        acc[2] = fma2(ap, pk2(w.z, w.z), acc[2]);
        acc[3] = fma2(ap, pk2(w.w, w.w), acc[3]);
    }
    #pragma unroll
    for (int nj = 0; nj < 4; ++nj) {
        float x0, x1;
        upk2(acc[nj], x0, x1);
        *reinterpret_cast<float2*>(Kout + (n3 + nj) * TM + m3) = make_float2(x0, x1);
    }
}

// ---------------- main fused Tsit5 kernel ----------------
__global__ void __launch_bounds__(NTH, 1)
ode_main(const float* __restrict__ x0, const float* __restrict__ uf,
         const float* __restrict__ b1, const float* __restrict__ b2,
         const float* __restrict__ b3, float* __restrict__ out) {
    extern __shared__ float smem[];
    float* A0 = smem;               // [512][16] stage input z (rows 0..255 used by W1) / W2 out
    float* A1 = A0 + DIN * TM;      // [512][16] W1 out
    float* BU = A1 + DIN * TM;      // [512][16] precomputed b1 + W1[:,256:]*u
    float* Y  = BU + DIN * TM;      // [256][16]
    float* U  = Y + DSTATE * TM;    // [256][16]
    float* KB = U + DSTATE * TM;    // [6][256][16]

    const int tid = threadIdx.x;
    const int r0 = blockIdx.x * TM;

    // init Y, U (column-major over m)
    for (int idx = tid; idx < TM * DSTATE; idx += NTH) {
        int m = idx >> 8, c = idx & 255;
        int r = r0 + m, traj = r & 1023;
        Y[c * TM + m] = x0[traj * DSTATE + c];
        U[c * TM + m] = (r < 1024) ? uf[traj * DSTATE + c] : 0.f;
    }
    __syncthreads();

    const int m0 = (tid & 3) * 4, n0 = (tid >> 2) * 4;  // gemm512 mapping
    const int m3 = (tid & 7) * 2, n3 = (tid >> 3) * 4;  // gemm256 mapping
    const int cc = tid >> 1, mh = (tid & 1) * 8;        // build mapping

    // BU = b1 + W1[:,256:512] @ u   (u constant across all stages/steps)
    gemm512<DSTATE, false, false>(U, g_W1T + (size_t)DSTATE * NW, b1, nullptr, BU, m0, n0);
    __syncthreads();

    const float H = 1.0f / 60.0f;
    #pragma unroll 1
    for (int step = 0; step < NSTEPS; ++step) {
        #pragma unroll 1
        for (int s = 0; s < 6; ++s) {
            // build stage input z = y + H * sum_j a_sj k_j  into A0 rows [0,256)
            #pragma unroll
            for (int q = 0; q < 2; ++q) {
                int off = cc * TM + mh + q * 4;
                float4 y = *reinterpret_cast<const float4*>(Y + off);
                float4 a = make_float4(0.f, 0.f, 0.f, 0.f);
                for (int j = 0; j < s; ++j) {
                    float4 kv = *reinterpret_cast<const float4*>(KB + j * (DSTATE * TM) + off);
                    float aj = c_A[s][j];
                    a.x += aj * kv.x; a.y += aj * kv.y;
                    a.z += aj * kv.z; a.w += aj * kv.w;
                }
                y.x += H * a.x; y.y += H * a.y; y.z += H * a.z; y.w += H * a.w;
                *reinterpret_cast<float4*>(A0 + off) = y;
            }
            __syncthreads();
            gemm512<DSTATE, true, true>(A0, g_W1T, nullptr, BU, A1, m0, n0);   // K=256!
            __syncthreads();
            gemm512<DIN, true, false>(A1, g_W2T, b2, nullptr, A0, m0, n0);
            __syncthreads();
            gemm256(A0, g_W3T, b3, KB + s * (DSTATE * TM), m3, n3);
            __syncthreads();
        }
        // y += H * sum_i b_i k_i
        #pragma unroll
        for (int q = 0; q < 2; ++q) {
            int off = cc * TM + mh + q * 4;
            float4 y = *reinterpret_cast<const float4*>(Y + off);
            float4 a = make_float4(0.f, 0.f, 0.f, 0.f);
            #pragma unroll
            for (int j = 0; j < 6; ++j) {
                float4 kv = *reinterpret_cast<const float4*>(KB + j * (DSTATE * TM) + off);
                float bj = c_Bw[j];
                a.x += bj * kv.x; a.y += bj * kv.y;
                a.z += bj * kv.z; a.w += bj * kv.w;
            }
            y.x += H * a.x; y.y += H * a.y; y.z += H * a.z; y.w += H * a.w;
            *reinterpret_cast<float4*>(Y + off) = y;
        }
        __syncthreads();
    }

    // out[(branch*1024 + traj)*256 + c] == out[r*256 + c]
    for (int idx = tid; idx < TM * DSTATE; idx += NTH) {
        int m = idx >> 8, c = idx & 255;
        out[(size_t)(r0 + m) * DSTATE + c] = Y[c * TM + m];
    }
}

// ---------------- launch ----------------
extern "C" void kernel_launch(void* const* d_in, const int* in_sizes, int n_in,
                              void* d_out, int out_size) {
    (void)in_sizes; (void)n_in; (void)out_size;
    const float* x0 = (const float*)d_in[0];
    const float* uf = (const float*)d_in[1];
    const float* W1 = (const float*)d_in[2];
    const float* b1 = (const float*)d_in[3];
    const float* W2 = (const float*)d_in[4];
    const float* b2 = (const float*)d_in[5];
    const float* W3 = (const float*)d_in[6];
    const float* b3 = (const float*)d_in[7];
    float* out = (float*)d_out;

    dim3 tthreads(32, 8);
    transpose_kernel<<<dim3(DIN / 32, NW / 32), tthreads>>>(0, W1, NW, DIN);
    transpose_kernel<<<dim3(NW / 32, NW / 32), tthreads>>>(1, W2, NW, NW);
    transpose_kernel<<<dim3(NW / 32, DSTATE / 32), tthreads>>>(2, W3, DSTATE, NW);

    size_t smem_bytes = (size_t)(3 * DIN * TM + 2 * DSTATE * TM + 6 * DSTATE * TM) * sizeof(float);
    cudaFuncSetAttribute(ode_main, cudaFuncAttributeMaxDynamicSharedMemorySize, (int)smem_bytes);
    ode_main<<<NBLOCKS, NTH, smem_bytes>>>(x0, uf, b1, b2, b3, out);
}